// round 15
// baseline (speedup 1.0000x reference)
#include <cuda_runtime.h>
#include <cuda_bf16.h>
#include <math.h>

// Proven skeleton (R0/R14): out itself is the election table.
//   memset: out = 0
//   elect:  atomicMax(out_i[cell], packed), packed = (pair+1)<<3 | bucket
//   write:  winner (out_i[cell]==packed) overwrites with float b[bucket]
// packed < 2^23 (positive int). Unique winner per cell -> race-free stores.

// Pass 1: election. 2 int4 quads per thread -> 6 coalesced loads + 8
// independent fire-and-forget REDG.MAX per thread (max MLP, no scoreboard).
__global__ void __launch_bounds__(256)
se_elect(const int4* __restrict__ src4,
         const int4* __restrict__ dst4,
         const int4* __restrict__ path_len4,
         int n_quads, int n_pairs, int nn, int max_path,
         int* __restrict__ out_i) {
    int q0 = (blockIdx.x * blockDim.x + threadIdx.x) * 2;

#pragma unroll
    for (int qq = 0; qq < 2; qq++) {
        int q = q0 + qq;
        if (q >= n_quads) return;

        int4 s4 = __ldg(&src4[q]);
        int4 d4 = __ldg(&dst4[q]);
        int4 p4 = __ldg(&path_len4[q]);

        int i0 = q * 4;
        int sv[4] = {s4.x, s4.y, s4.z, s4.w};
        int dv[4] = {d4.x, d4.y, d4.z, d4.w};
        int pv[4] = {p4.x, p4.y, p4.z, p4.w};

#pragma unroll
        for (int k = 0; k < 4; k++) {
            int i = i0 + k;
            if (i < n_pairs) {
                int bu = (pv[k] < max_path ? pv[k] : max_path) - 1;
                if (bu < 0) bu = 0;
                unsigned cell = (unsigned)sv[k] * (unsigned)nn + (unsigned)dv[k];
                atomicMax(&out_i[cell], ((i + 1) << 3) | bu);  // fire-and-forget
            }
        }
    }
}

// Pass 2: winners convert packed -> float. One int4 quad per thread: 3
// coalesced loads, then ALL FOUR random reads issued back-to-back (4x MLP)
// before any compare/store. Reads hit lines elect just dirtied in L2.
__global__ void __launch_bounds__(256)
se_write(const float* __restrict__ b,
         const int4* __restrict__ src4,
         const int4* __restrict__ dst4,
         const int4* __restrict__ path_len4,
         int n_quads, int n_pairs, int nn, int max_path,
         int* __restrict__ out_i,
         float* __restrict__ out_f) {
    int q = blockIdx.x * blockDim.x + threadIdx.x;
    if (q >= n_quads) return;

    int4 s4 = __ldg(&src4[q]);
    int4 d4 = __ldg(&dst4[q]);
    int4 p4 = __ldg(&path_len4[q]);

    int i0 = q * 4;
    int sv[4] = {s4.x, s4.y, s4.z, s4.w};
    int dv[4] = {d4.x, d4.y, d4.z, d4.w};
    int pv[4] = {p4.x, p4.y, p4.z, p4.w};

    unsigned cell[4];
    int packed[4], bu[4], w[4];
    bool act[4];

#pragma unroll
    for (int k = 0; k < 4; k++) {
        int i = i0 + k;
        act[k] = (i < n_pairs);
        if (act[k]) {
            int t = (pv[k] < max_path ? pv[k] : max_path) - 1;
            bu[k] = t < 0 ? 0 : t;
            packed[k] = ((i + 1) << 3) | bu[k];
            cell[k] = (unsigned)sv[k] * (unsigned)nn + (unsigned)dv[k];
        }
    }
    // 4 independent random reads in flight together
#pragma unroll
    for (int k = 0; k < 4; k++)
        if (act[k]) w[k] = __ldcg(&out_i[cell[k]]);
#pragma unroll
    for (int k = 0; k < 4; k++)
        if (act[k] && w[k] == packed[k])
            out_f[cell[k]] = __ldg(&b[bu[k]]);
}

extern "C" void kernel_launch(void* const* d_in, const int* in_sizes, int n_in,
                              void* d_out, int out_size) {
    // inputs: x [n_nodes,128] f32 (unused), b [max_path] f32,
    //         src [n_pairs] i32, dst [n_pairs] i32, path_len [n_pairs] i32
    const float* b        = (const float*)d_in[1];
    const int*   src      = (const int*)d_in[2];
    const int*   dst      = (const int*)d_in[3];
    const int*   path_len = (const int*)d_in[4];

    int max_path = in_sizes[1];
    int n_pairs  = in_sizes[2];
    int nn = (int)(sqrt((double)out_size) + 0.5);

    int*   out_i = (int*)d_out;
    float* out_f = (float*)d_out;

    const int T = 256;
    int n_quads = (n_pairs + 3) / 4;

    // 1) mandatory 256MB zero-fill at CE speed (also zeroes the elect table)
    cudaMemsetAsync(d_out, 0, (size_t)out_size * sizeof(float), 0);

    // 2) election: 8 pairs/thread, fire-and-forget REDG.MAX
    int blocksA = (n_quads + T * 2 - 1) / (T * 2);
    se_elect<<<blocksA, T>>>((const int4*)src, (const int4*)dst,
                             (const int4*)path_len,
                             n_quads, n_pairs, nn, max_path, out_i);

    // 3) winners convert packed -> float, 4 batched random reads per thread
    int blocksB = (n_quads + T - 1) / T;
    se_write<<<blocksB, T>>>(b, (const int4*)src, (const int4*)dst,
                             (const int4*)path_len,
                             n_quads, n_pairs, nn, max_path, out_i, out_f);
}